// round 4
// baseline (speedup 1.0000x reference)
#include <cuda_runtime.h>
#include <cuda_bf16.h>
#include <math.h>
#include <stdint.h>

#define NN 10000
#define EE 160000
#define ET 170000   // edges + self loops

// ---------------- scratch (device globals; no allocations allowed) ----------
__device__ float g_hmat[NN * 2048];
__device__ float g_es  [NN * 4];
__device__ float g_ed  [NN * 4];
__device__ float g_alpha[ET * 4];
__device__ int   g_counts [NN];
__device__ int   g_rowptr [NN + 1];
__device__ int   g_fillpos[NN];
__device__ int   g_csrsrc [ET];
__device__ int   g_is64;
// bf16 hi/lo activation pairs (ping-pong) + weight pair
__device__ __align__(16) __nv_bfloat16 g_P0h[NN * 2048];
__device__ __align__(16) __nv_bfloat16 g_P0l[NN * 2048];
__device__ __align__(16) __nv_bfloat16 g_P1h[NN * 2048];
__device__ __align__(16) __nv_bfloat16 g_P1l[NN * 2048];
__device__ __align__(16) __nv_bfloat16 g_Wh[2048 * 2048];
__device__ __align__(16) __nv_bfloat16 g_Wl[2048 * 2048];

// ============================ PTX helpers (baseline, sm_80+) =================
__device__ __forceinline__ uint32_t smem_to_u32(const void* p) {
    uint32_t a;
    asm("{ .reg .u64 t; cvta.to.shared.u64 t, %1; cvt.u32.u64 %0, t; }" : "=r"(a) : "l"(p));
    return a;
}

__device__ __forceinline__ void cp16(uint32_t dst, const void* src, bool v) {
    int sz = v ? 16 : 0;
    asm volatile("cp.async.cg.shared.global [%0], [%1], 16, %2;\n"
                 :: "r"(dst), "l"(src), "r"(sz) : "memory");
}
#define CP_COMMIT() asm volatile("cp.async.commit_group;" ::: "memory")
#define CP_WAIT1()  asm volatile("cp.async.wait_group 1;" ::: "memory")

__device__ __forceinline__ void ldsm4(uint32_t* r, uint32_t addr) {
    asm volatile("ldmatrix.sync.aligned.m8n8.x4.shared.b16 {%0,%1,%2,%3}, [%4];"
                 : "=r"(r[0]), "=r"(r[1]), "=r"(r[2]), "=r"(r[3]) : "r"(addr));
}

__device__ __forceinline__ void mma16816(float* c, const uint32_t* a, const uint32_t* b) {
    asm volatile(
        "mma.sync.aligned.m16n8k16.row.col.f32.bf16.bf16.f32 "
        "{%0,%1,%2,%3}, {%4,%5,%6,%7}, {%8,%9}, {%0,%1,%2,%3};"
        : "+f"(c[0]), "+f"(c[1]), "+f"(c[2]), "+f"(c[3])
        : "r"(a[0]), "r"(a[1]), "r"(a[2]), "r"(a[3]), "r"(b[0]), "r"(b[1]));
}

__device__ __forceinline__ int edge_at(const void* ei, long long idx) {
    if (g_is64) return (int)((const long long*)ei)[idx];
    return ((const int*)ei)[idx];
}

// ---------------- CSR build ---------------------------------------------------
__global__ void detect_init_kernel(const unsigned int* p) {
    int i = blockIdx.x * blockDim.x + threadIdx.x;
    if (i < NN) g_counts[i] = 1;           // self loop pre-counted
    if (i == 0) {
        int is64 = 1;
        for (int j = 0; j < 128; j++)
            if (p[2 * j + 1] != 0u) { is64 = 0; break; }
        g_is64 = is64;
    }
}
__global__ void count_kernel(const void* ei) {
    int e = blockIdx.x * blockDim.x + threadIdx.x;
    if (e < EE) atomicAdd(&g_counts[edge_at(ei, (long long)EE + e)], 1);
}
__global__ void scan_fillself_kernel() {
    __shared__ int sh[1024];
    int t = threadIdx.x;
    const int chunk = (NN + 1023) >> 10;
    int base = t * chunk;
    int s = 0;
    for (int j = 0; j < chunk; j++) { int idx = base + j; if (idx < NN) s += g_counts[idx]; }
    sh[t] = s;
    __syncthreads();
    for (int off = 1; off < 1024; off <<= 1) {
        int v = (t >= off) ? sh[t - off] : 0;
        __syncthreads();
        sh[t] += v;
        __syncthreads();
    }
    int prefix = (t > 0) ? sh[t - 1] : 0;
    for (int j = 0; j < chunk; j++) {
        int idx = base + j;
        if (idx < NN) { g_rowptr[idx] = prefix; prefix += g_counts[idx]; }
    }
    if (t == 0) g_rowptr[NN] = sh[1023];
    __syncthreads();
    // fillself: self loop at row head (deterministic order)
    for (int idx = t; idx < NN; idx += 1024) {
        int r = g_rowptr[idx];
        g_csrsrc[r] = idx;
        g_fillpos[idx] = r + 1;
    }
}
__global__ void filledges_kernel(const void* ei) {
    int e = blockIdx.x * blockDim.x + threadIdx.x;
    if (e < EE) {
        int s = edge_at(ei, e);
        int d = edge_at(ei, (long long)EE + e);
        g_csrsrc[atomicAdd(&g_fillpos[d], 1)] = s;
    }
}

// ---------------- fp32 -> bf16 hi/lo split (only for input x) ----------------
__global__ void cvt_split_kernel(const float* __restrict__ x,
                                 __nv_bfloat16* __restrict__ hi,
                                 __nv_bfloat16* __restrict__ lo, int n4) {
    int i = blockIdx.x * blockDim.x + threadIdx.x;
    if (i >= n4) return;
    float4 v = ((const float4*)x)[i];
    __nv_bfloat16 h0 = __float2bfloat16(v.x);
    __nv_bfloat16 h1 = __float2bfloat16(v.y);
    __nv_bfloat16 h2 = __float2bfloat16(v.z);
    __nv_bfloat16 h3 = __float2bfloat16(v.w);
    __nv_bfloat16 l0 = __float2bfloat16(v.x - __bfloat162float(h0));
    __nv_bfloat16 l1 = __float2bfloat16(v.y - __bfloat162float(h1));
    __nv_bfloat16 l2 = __float2bfloat16(v.z - __bfloat162float(h2));
    __nv_bfloat16 l3 = __float2bfloat16(v.w - __bfloat162float(h3));
    ((__nv_bfloat162*)hi)[2 * i]     = __nv_bfloat162(h0, h1);
    ((__nv_bfloat162*)hi)[2 * i + 1] = __nv_bfloat162(h2, h3);
    ((__nv_bfloat162*)lo)[2 * i]     = __nv_bfloat162(l0, l1);
    ((__nv_bfloat162*)lo)[2 * i + 1] = __nv_bfloat162(l2, l3);
}

// ---------------- weight transpose + split: W[K,N] -> Wt[N,K] hi/lo ----------
__global__ void cvt_transpose_kernel(const float* __restrict__ W,
                                     __nv_bfloat16* __restrict__ th,
                                     __nv_bfloat16* __restrict__ tl, int K, int N) {
    __shared__ float tile[32][33];
    int n0 = blockIdx.x * 32, k0 = blockIdx.y * 32;
    int tx = threadIdx.x, ty = threadIdx.y;   // 32 x 8
    for (int r = ty; r < 32; r += 8)
        tile[r][tx] = W[(size_t)(k0 + r) * N + n0 + tx];
    __syncthreads();
    for (int r = ty; r < 32; r += 8) {
        float v = tile[tx][r];   // = W[k0+tx][n0+r]
        __nv_bfloat16 h = __float2bfloat16(v);
        size_t o = (size_t)(n0 + r) * K + k0 + tx;
        th[o] = h;
        tl[o] = __float2bfloat16(v - __bfloat162float(h));
    }
}

// ---------------- mma.sync bf16x3 GEMM ----------------------------------------
// CTA tile 128(M) x 256(N), BK=64, 2-stage cp.async double-buffer,
// 8 warps (2 M x 4 N), warp tile 64x64.
// EPI 0: fp32 out (+bias). EPI 1: bf16 hi/lo split out (+bias).
#define GA 16384                      // one A operand buffer (128 rows x 128B)
#define GB 32768                      // one B operand buffer (256 rows x 128B)
#define GSTAGE (2 * GA + 2 * GB)      // 98304
#define GSMEM  (2 * GSTAGE)           // 196608

__device__ __forceinline__ uint32_t swz(uint32_t base, int row, int kelem) {
    return base + row * 128 + ((((kelem >> 3) ^ row) & 7) << 4);
}

__device__ __forceinline__ void load_stage(
    uint32_t sbase,
    const __nv_bfloat16* __restrict__ Ah, const __nv_bfloat16* __restrict__ Al,
    const __nv_bfloat16* __restrict__ Bh, const __nv_bfloat16* __restrict__ Bl,
    int m0, int n0, int M, int K, int j, int tid)
{
    const int lrow = tid >> 3;            // 0..31
    const int lchk = tid & 7;             // 16B chunk within 128B row
    const long long k0 = (long long)j << 6;
#pragma unroll
    for (int it = 0; it < 4; it++) {       // A: 128 rows
        int row = lrow + it * 32;
        bool av = (m0 + row < M);
        int gr = av ? (m0 + row) : 0;
        size_t aoff = (size_t)gr * K + k0 + lchk * 8;
        uint32_t d = swz(sbase, row, lchk * 8);
        cp16(d,      Ah + aoff, av);
        cp16(d + GA, Al + aoff, av);
    }
#pragma unroll
    for (int it = 0; it < 8; it++) {       // B: 256 rows (always in-bounds)
        int row = lrow + it * 32;
        size_t boff = (size_t)(n0 + row) * K + k0 + lchk * 8;
        uint32_t d = swz(sbase + 2 * GA, row, lchk * 8);
        cp16(d,      Bh + boff, true);
        cp16(d + GB, Bl + boff, true);
    }
}

template <int EPI>
__global__ void __launch_bounds__(256, 1) gemm_mma_kernel(
    const __nv_bfloat16* __restrict__ Ah, const __nv_bfloat16* __restrict__ Al,
    const __nv_bfloat16* __restrict__ Bh, const __nv_bfloat16* __restrict__ Bl,
    const float* __restrict__ bias, float* __restrict__ Cf,
    __nv_bfloat16* __restrict__ Ch, __nv_bfloat16* __restrict__ Cl,
    int M, int N, int K)
{
    extern __shared__ char smem[];
    const uint32_t sb = smem_to_u32(smem);
    const int tid = threadIdx.x;
    const int lane = tid & 31, wid = tid >> 5;
    const int m0 = blockIdx.y * 128, n0 = blockIdx.x * 256;
    const int nk = K >> 6;

    float acc[4][8][4];
#pragma unroll
    for (int a = 0; a < 4; a++)
#pragma unroll
        for (int b = 0; b < 8; b++)
#pragma unroll
            for (int c = 0; c < 4; c++) acc[a][b][c] = 0.f;

    load_stage(sb,          Ah, Al, Bh, Bl, m0, n0, M, K, 0, tid);
    CP_COMMIT();
    load_stage(sb + GSTAGE, Ah, Al, Bh, Bl, m0, n0, M, K, 1, tid);
    CP_COMMIT();

    const int mw = (wid & 1) * 64;     // warp M offset
    const int nw = (wid >> 1) * 64;    // warp N offset
    const int rsel = lane & 15;
    const int khalf = (lane >> 4) * 8;

    for (int i = 0; i < nk; i++) {
        CP_WAIT1();
        __syncthreads();
        const uint32_t sA = sb + (uint32_t)(i & 1) * GSTAGE;
        const uint32_t sB = sA + 2 * GA;
#pragma unroll
        for (int ks = 0; ks < 4; ks++) {
            const int ke = ks * 16 + khalf;
            uint32_t ah[4][4], al[4][4];
#pragma unroll
            for (int mi = 0; mi < 4; mi++) {
                uint32_t ad = swz(sA, mw + mi * 16 + rsel, ke);
                ldsm4(ah[mi], ad);
                ldsm4(al[mi], ad + GA);
            }
#pragma unroll
            for (int bi = 0; bi < 4; bi++) {
                uint32_t bh[4], bl[4];
                uint32_t bd = swz(sB, nw + bi * 16 + rsel, ke);
                ldsm4(bh, bd);
                ldsm4(bl, bd + GB);
#pragma unroll
                for (int nj2 = 0; nj2 < 2; nj2++) {
                    const int nj = bi * 2 + nj2;
                    uint32_t b2h[2] = { bh[nj2], bh[nj2 + 2] };
                    uint32_t b2l[2] = { bl[nj2], bl[nj2 + 2] };
#pragma unroll
                    for (int mi = 0; mi < 4; mi++) {
                        mma16816(acc[mi][nj], ah[mi], b2h);
                        mma16816(acc[mi][nj], ah[mi], b2l);
                        mma16816(acc[mi][nj], al[mi], b2h);
                    }
                }
            }
        }
        __syncthreads();
        if (i + 2 < nk)
            load_stage(sb + (uint32_t)(i & 1) * GSTAGE, Ah, Al, Bh, Bl, m0, n0, M, K, i + 2, tid);
        CP_COMMIT();   // unconditional: keeps group accounting aligned
    }

    // epilogue
#pragma unroll
    for (int mi = 0; mi < 4; mi++) {
#pragma unroll
        for (int nj = 0; nj < 8; nj++) {
            int col = n0 + nw + nj * 8 + (lane & 3) * 2;
            float bx = 0.f, by = 0.f;
            if (bias) { bx = bias[col]; by = bias[col + 1]; }
            int r0 = m0 + mw + mi * 16 + (lane >> 2);
            int r1 = r0 + 8;
            if (EPI == 0) {
                if (r0 < M)
                    *(float2*)(Cf + (size_t)r0 * N + col) =
                        make_float2(acc[mi][nj][0] + bx, acc[mi][nj][1] + by);
                if (r1 < M)
                    *(float2*)(Cf + (size_t)r1 * N + col) =
                        make_float2(acc[mi][nj][2] + bx, acc[mi][nj][3] + by);
            } else {
                if (r0 < M) {
                    float v0 = acc[mi][nj][0] + bx, v1 = acc[mi][nj][1] + by;
                    __nv_bfloat16 h0 = __float2bfloat16(v0), h1 = __float2bfloat16(v1);
                    size_t o = ((size_t)r0 * N + col) >> 1;
                    ((__nv_bfloat162*)Ch)[o] = __nv_bfloat162(h0, h1);
                    ((__nv_bfloat162*)Cl)[o] = __nv_bfloat162(
                        __float2bfloat16(v0 - __bfloat162float(h0)),
                        __float2bfloat16(v1 - __bfloat162float(h1)));
                }
                if (r1 < M) {
                    float v0 = acc[mi][nj][2] + bx, v1 = acc[mi][nj][3] + by;
                    __nv_bfloat16 h0 = __float2bfloat16(v0), h1 = __float2bfloat16(v1);
                    size_t o = ((size_t)r1 * N + col) >> 1;
                    ((__nv_bfloat162*)Ch)[o] = __nv_bfloat162(h0, h1);
                    ((__nv_bfloat162*)Cl)[o] = __nv_bfloat162(
                        __float2bfloat16(v0 - __bfloat162float(h0)),
                        __float2bfloat16(v1 - __bfloat162float(h1)));
                }
            }
        }
    }
}

// ---------------- per-node attention coefficients es/ed ----------------------
__global__ void attn_kernel(const float* __restrict__ hmat,
                            const float* __restrict__ a_src,
                            const float* __restrict__ a_dst, int H) {
    const int C = 512;
    int i = blockIdx.x;
    int hh = threadIdx.x >> 5;
    int lane = threadIdx.x & 31;
    const float* hr = hmat + (size_t)i * H * C + hh * C;
    float s = 0.f, d = 0.f;
    for (int c = lane; c < C; c += 32) {
        float v = hr[c];
        s += v * a_src[hh * C + c];
        d += v * a_dst[hh * C + c];
    }
#pragma unroll
    for (int o = 16; o > 0; o >>= 1) {
        s += __shfl_xor_sync(0xffffffffu, s, o);
        d += __shfl_xor_sync(0xffffffffu, d, o);
    }
    if (lane == 0) { g_es[i * H + hh] = s; g_ed[i * H + hh] = d; }
}

// ---------------- segment softmax over dst-CSR rows --------------------------
__global__ void softmax_kernel(int H) {
    int idx = blockIdx.x * blockDim.x + threadIdx.x;
    if (idx >= NN * H) return;
    int i = idx % NN;
    int hh = idx / NN;
    float edi = g_ed[i * H + hh];
    int p0 = g_rowptr[i], p1 = g_rowptr[i + 1];
    float m = -1e30f;
    for (int p = p0; p < p1; p++) {
        float e = g_es[g_csrsrc[p] * H + hh] + edi;
        e = (e > 0.f) ? e : 0.2f * e;
        m = fmaxf(m, e);
    }
    float den = 0.f;
    for (int p = p0; p < p1; p++) {
        float e = g_es[g_csrsrc[p] * H + hh] + edi;
        e = (e > 0.f) ? e : 0.2f * e;
        float a = expf(e - m);
        g_alpha[p * 4 + hh] = a;
        den += a;
    }
    float inv = 1.f / den;
    for (int p = p0; p < p1; p++) g_alpha[p * 4 + hh] *= inv;
}

// ---------------- weighted aggregation (float4) ------------------------------
// MODE 0: concat heads + bias + ELU, write bf16 hi/lo split (next GEMM input).
// MODE 1: mean over 2 heads + bias, write fp32.
template <int HC, int MODE>
__global__ void aggregate_kernel(const float* __restrict__ hmat,
                                 const float* __restrict__ bias,
                                 float* __restrict__ outF,
                                 __nv_bfloat16* __restrict__ outH,
                                 __nv_bfloat16* __restrict__ outL) {
    constexpr int PT = HC / 1024;            // float4s per thread
    int i = blockIdx.x;
    int t = threadIdx.x;
    int hsel = t >> 7;                        // 0 or 1
    float4 acc[PT];
#pragma unroll
    for (int k = 0; k < PT; k++) acc[k] = make_float4(0.f, 0.f, 0.f, 0.f);

    int p0 = g_rowptr[i], p1 = g_rowptr[i + 1];
    for (int p = p0; p < p1; p++) {
        int s = g_csrsrc[p];
        float4 a4 = *(const float4*)(g_alpha + p * 4);
        const float* al = (const float*)&a4;
        const float4* hr = (const float4*)(hmat + (size_t)s * HC);
#pragma unroll
        for (int k = 0; k < PT; k++) {
            float av = al[2 * k + hsel];
            float4 h = hr[t + k * 256];
            acc[k].x += av * h.x;
            acc[k].y += av * h.y;
            acc[k].z += av * h.z;
            acc[k].w += av * h.w;
        }
    }

    if (MODE == 0) {
#pragma unroll
        for (int k = 0; k < PT; k++) {
            int col4 = t + k * 256;
            float4 b = *(const float4*)(bias + col4 * 4);
            float4 v = acc[k];
            v.x += b.x; v.y += b.y; v.z += b.z; v.w += b.w;
            v.x = (v.x > 0.f) ? v.x : (expf(v.x) - 1.f);
            v.y = (v.y > 0.f) ? v.y : (expf(v.y) - 1.f);
            v.z = (v.z > 0.f) ? v.z : (expf(v.z) - 1.f);
            v.w = (v.w > 0.f) ? v.w : (expf(v.w) - 1.f);
            __nv_bfloat16 h0 = __float2bfloat16(v.x), h1 = __float2bfloat16(v.y);
            __nv_bfloat16 h2 = __float2bfloat16(v.z), h3 = __float2bfloat16(v.w);
            size_t o2 = ((size_t)i * HC + col4 * 4) >> 1;
            ((__nv_bfloat162*)outH)[o2]     = __nv_bfloat162(h0, h1);
            ((__nv_bfloat162*)outH)[o2 + 1] = __nv_bfloat162(h2, h3);
            ((__nv_bfloat162*)outL)[o2] = __nv_bfloat162(
                __float2bfloat16(v.x - __bfloat162float(h0)),
                __float2bfloat16(v.y - __bfloat162float(h1)));
            ((__nv_bfloat162*)outL)[o2 + 1] = __nv_bfloat162(
                __float2bfloat16(v.z - __bfloat162float(h2)),
                __float2bfloat16(v.w - __bfloat162float(h3)));
        }
    } else {
        __shared__ float4 sh[256];
        sh[t] = acc[0];
        __syncthreads();
        if (t < 128) {
            float4 v0 = sh[t], v1 = sh[t + 128];
            float4 b = ((const float4*)bias)[t];
            float4 r;
            r.x = 0.5f * (v0.x + v1.x) + b.x;
            r.y = 0.5f * (v0.y + v1.y) + b.y;
            r.z = 0.5f * (v0.z + v1.z) + b.z;
            r.w = 0.5f * (v0.w + v1.w) + b.w;
            ((float4*)outF)[(size_t)i * 128 + t] = r;
        }
    }
}

// ---------------- host launch helpers ----------------------------------------
static void run_gemm_f32(const __nv_bfloat16* ah, const __nv_bfloat16* al,
                         const __nv_bfloat16* wh, const __nv_bfloat16* wl,
                         const float* bias, float* C, int M, int N, int K) {
    dim3 grid(N / 256, (M + 127) / 128);
    gemm_mma_kernel<0><<<grid, 256, GSMEM>>>(ah, al, wh, wl, bias, C, nullptr, nullptr, M, N, K);
}
static void run_gemm_split(const __nv_bfloat16* ah, const __nv_bfloat16* al,
                           const __nv_bfloat16* wh, const __nv_bfloat16* wl,
                           const float* bias, __nv_bfloat16* ch, __nv_bfloat16* cl,
                           int M, int N, int K) {
    dim3 grid(N / 256, (M + 127) / 128);
    gemm_mma_kernel<1><<<grid, 256, GSMEM>>>(ah, al, wh, wl, bias, nullptr, ch, cl, M, N, K);
}

extern "C" void kernel_launch(void* const* d_in, const int* in_sizes, int n_in,
                              void* d_out, int out_size) {
    const float* x      = (const float*)d_in[0];
    const void*  ei     = d_in[1];
    const float* proj_w = (const float*)d_in[2];
    const float* proj_b = (const float*)d_in[3];
    const float* w1  = (const float*)d_in[4];
    const float* as1 = (const float*)d_in[5];
    const float* ad1 = (const float*)d_in[6];
    const float* b1  = (const float*)d_in[7];
    const float* w2  = (const float*)d_in[8];
    const float* as2 = (const float*)d_in[9];
    const float* ad2 = (const float*)d_in[10];
    const float* b2  = (const float*)d_in[11];
    const float* w3  = (const float*)d_in[12];
    const float* as3 = (const float*)d_in[13];
    const float* ad3 = (const float*)d_in[14];
    const float* b3  = (const float*)d_in[15];
    float* out = (float*)d_out;

    float* hmat;
    __nv_bfloat16 *P0h, *P0l, *P1h, *P1l, *Wh, *Wl;
    cudaGetSymbolAddress((void**)&hmat, g_hmat);
    cudaGetSymbolAddress((void**)&P0h, g_P0h);
    cudaGetSymbolAddress((void**)&P0l, g_P0l);
    cudaGetSymbolAddress((void**)&P1h, g_P1h);
    cudaGetSymbolAddress((void**)&P1l, g_P1l);
    cudaGetSymbolAddress((void**)&Wh, g_Wh);
    cudaGetSymbolAddress((void**)&Wl, g_Wl);

    static bool attr_set = false;
    if (!attr_set) {
        cudaFuncSetAttribute(gemm_mma_kernel<0>,
                             cudaFuncAttributeMaxDynamicSharedMemorySize, GSMEM);
        cudaFuncSetAttribute(gemm_mma_kernel<1>,
                             cudaFuncAttributeMaxDynamicSharedMemorySize, GSMEM);
        attr_set = true;
    }

    // launch 0/1: x split + proj_w transpose (independent of CSR)
    cvt_split_kernel<<<(NN * 256 / 4 + 255) / 256, 256>>>(x, P0h, P0l, NN * 256 / 4);
    cvt_transpose_kernel<<<dim3(512 / 32, 256 / 32), dim3(32, 8)>>>(proj_w, Wh, Wl, 256, 512);
    // launch 2-4: CSR counts + scan (+self loops)
    detect_init_kernel<<<(NN + 255) / 256, 256>>>((const unsigned int*)ei);
    count_kernel<<<(EE + 255) / 256, 256>>>(ei);
    scan_fillself_kernel<<<1, 1024>>>();
    // launch 5: projection GEMM (ncu -s 5 -c 1 captures this one)
    run_gemm_split(P0h, P0l, Wh, Wl, proj_b, P1h, P1l, NN, 512, 256);
    // CSR edge fill (needed before softmax/aggregate only)
    filledges_kernel<<<(EE + 255) / 256, 256>>>(ei);

    // ---- GAT layer 1 (H=4, C=512, concat, ELU): N=2048, K=512 ----
    cvt_transpose_kernel<<<dim3(2048 / 32, 512 / 32), dim3(32, 8)>>>(w1, Wh, Wl, 512, 2048);
    run_gemm_f32(P1h, P1l, Wh, Wl, nullptr, hmat, NN, 2048, 512);
    attn_kernel<<<NN, 128>>>(hmat, as1, ad1, 4);
    softmax_kernel<<<(NN * 4 + 255) / 256, 256>>>(4);
    aggregate_kernel<2048, 0><<<NN, 256>>>(hmat, b1, nullptr, P0h, P0l);

    // ---- GAT layer 2 (H=4, C=512, concat, ELU): N=2048, K=2048 ----
    cvt_transpose_kernel<<<dim3(2048 / 32, 2048 / 32), dim3(32, 8)>>>(w2, Wh, Wl, 2048, 2048);
    run_gemm_f32(P0h, P0l, Wh, Wl, nullptr, hmat, NN, 2048, 2048);
    attn_kernel<<<NN, 128>>>(hmat, as2, ad2, 4);
    softmax_kernel<<<(NN * 4 + 255) / 256, 256>>>(4);
    aggregate_kernel<2048, 0><<<NN, 256>>>(hmat, b2, nullptr, P1h, P1l);

    // ---- GAT layer 3 (H=2, C=512, mean): N=1024, K=2048 ----
    cvt_transpose_kernel<<<dim3(1024 / 32, 2048 / 32), dim3(32, 8)>>>(w3, Wh, Wl, 2048, 1024);
    run_gemm_f32(P1h, P1l, Wh, Wl, nullptr, hmat, NN, 1024, 2048);
    attn_kernel<<<NN, 64>>>(hmat, as3, ad3, 2);
    softmax_kernel<<<(NN * 2 + 255) / 256, 256>>>(2);
    aggregate_kernel<1024, 1><<<NN, 256>>>(hmat, b3, out, nullptr, nullptr);
}